// round 15
// baseline (speedup 1.0000x reference)
#include <cuda_runtime.h>
#include <cmath>
#include <cstring>

#define FRAME 2048
#define IDX(i) ((i) ^ (((i) >> 4) & 15))   // float2 FFT-buffer swizzle
#define SSW(i) ((i) ^ (((i) >> 5) & 31))   // float scan-array swizzle

// ---- device-global tables, filled from host via async memcpy-to-symbol ----
__device__ float4 g_lagpack[2048];    // (lag, floor_bits, ceil_bits, 0)
__device__ float2 g_twtab[2048];      // T[n] = e^{-i pi n / 1024}

__device__ __forceinline__ float2 cmul(float2 a, float2 b) {
    return make_float2(fmaf(a.x, b.x, -a.y * b.y), fmaf(a.x, b.y, a.y * b.x));
}
// a * conj(b)
__device__ __forceinline__ float2 cmulc(float2 a, float2 b) {
    return make_float2(fmaf(a.x, b.x, a.y * b.y), fmaf(a.y, b.x, -a.x * b.y));
}
__device__ __forceinline__ float2 cadd(float2 a, float2 b) { return make_float2(a.x + b.x, a.y + b.y); }
__device__ __forceinline__ float2 csub(float2 a, float2 b) { return make_float2(a.x - b.x, a.y - b.y); }

template<bool INV>
__device__ __forceinline__ void dft4(float2 a, float2 b, float2 c, float2 d, float2* o) {
    float2 p = cadd(a, c), m = csub(a, c);
    float2 q = cadd(b, d), n = csub(b, d);
    o[0] = cadd(p, q);
    o[2] = csub(p, q);
    if (!INV) { o[1] = make_float2(m.x + n.y, m.y - n.x); o[3] = make_float2(m.x - n.y, m.y + n.x); }
    else      { o[1] = make_float2(m.x - n.y, m.y + n.x); o[3] = make_float2(m.x + n.y, m.y - n.x); }
}

template<bool INV>
__device__ __forceinline__ void omega8(const float2* O, float2& o1, float2& o2, float2& o3) {
    const float s2 = 0.70710678118654752f;
    if (!INV) {
        o1 = make_float2(s2 * (O[1].x + O[1].y), s2 * (O[1].y - O[1].x));
        o2 = make_float2(O[2].y, -O[2].x);
        o3 = make_float2(s2 * (O[3].y - O[3].x), -s2 * (O[3].x + O[3].y));
    } else {
        o1 = make_float2(s2 * (O[1].x - O[1].y), s2 * (O[1].y + O[1].x));
        o2 = make_float2(-O[2].y, O[2].x);
        o3 = make_float2(-s2 * (O[3].x + O[3].y), s2 * (O[3].x - O[3].y));
    }
}

// full DFT-8, natural-order outputs
template<bool INV>
__device__ __forceinline__ void dft8(const float2* u, float2* X) {
    float2 E[4], O[4];
    dft4<INV>(u[0], u[2], u[4], u[6], E);
    dft4<INV>(u[1], u[3], u[5], u[7], O);
    float2 o1, o2, o3;
    omega8<INV>(O, o1, o2, o3);
    X[0] = cadd(E[0], O[0]); X[4] = csub(E[0], O[0]);
    X[1] = cadd(E[1], o1);   X[5] = csub(E[1], o1);
    X[2] = cadd(E[2], o2);   X[6] = csub(E[2], o2);
    X[3] = cadd(E[3], o3);   X[7] = csub(E[3], o3);
}

// ω16^K * o (K = 1..7 compile-time), conjugated for inverse
template<int K, bool INV>
__device__ __forceinline__ float2 w16term(float2 o) {
    const float c8 = 0.92387953251128674f;
    const float s8 = 0.38268343236508978f;
    const float s2 = 0.70710678118654752f;
    const float sg = INV ? 1.f : -1.f;
    if (K == 4) return INV ? make_float2(-o.y, o.x) : make_float2(o.y, -o.x);
    float2 w;
    if (K == 1) w = make_float2( c8, sg * s8);
    if (K == 2) w = make_float2( s2, sg * s2);
    if (K == 3) w = make_float2( s8, sg * c8);
    if (K == 5) w = make_float2(-s8, sg * c8);
    if (K == 6) w = make_float2(-s2, sg * s2);
    if (K == 7) w = make_float2(-c8, sg * s8);
    return cmul(o, w);
}

// compile-time store-offset constant (NS=1 used by radix-8 stages)
template<int NS>
__device__ __forceinline__ constexpr int soff(int m) {
    return NS == 1 ? m
         : NS == 8 ? ((m << 3) | ((m >> 1) & 3))
                   : ((m << 6) | ((m & 3) << 2));
}
template<int NS>
__device__ __forceinline__ int sbase(int t) {
    if (NS == 1)  return (8 * t) ^ ((t >> 1) & 15);
    if (NS == 8)  return (((t >> 3) << 6) | (t & 7)) ^ (((t >> 3) & 3) << 2);
    /* NS == 64 */ return (((t >> 6) << 9) | (t & 63)) ^ ((t >> 4) & 3);
}

// ---- generic radix-8 Stockham stage (smem -> smem); used for inverse NS=1 ----
template<int NS, bool INV>
__device__ __forceinline__ void stage_r8(const float2* in, float2* out, int t, int tld) {
    float2 v[8];
#pragma unroll
    for (int k = 0; k < 8; k++) v[k] = in[tld + 256 * k];
    if (NS > 1) {
        const int jm = t & (NS - 1);
        float s, c;
        sincospif((float)jm * (1.0f / (4.0f * NS)), &s, &c);
        if (!INV) s = -s;
        float2 w1 = make_float2(c, s);
        v[1] = cmul(v[1], w1);
        float2 w2 = cmul(w1, w1);
        v[2] = cmul(v[2], w2);
        float2 w3 = cmul(w2, w1);
        v[3] = cmul(v[3], w3);
        float2 w4 = cmul(w2, w2);
        v[4] = cmul(v[4], w4);
        v[5] = cmul(v[5], cmul(w4, w1));
        v[6] = cmul(v[6], cmul(w4, w2));
        v[7] = cmul(v[7], cmul(w4, w3));
    }
    float2 X[8];
    dft8<INV>(v, X);
    const int b2 = sbase<NS>(t);
    out[b2 ^ soff<NS>(0)] = X[0];
    out[b2 ^ soff<NS>(4)] = X[4];
    out[b2 ^ soff<NS>(1)] = X[1];
    out[b2 ^ soff<NS>(5)] = X[5];
    out[b2 ^ soff<NS>(2)] = X[2];
    out[b2 ^ soff<NS>(6)] = X[6];
    out[b2 ^ soff<NS>(3)] = X[3];
    out[b2 ^ soff<NS>(7)] = X[7];
    __syncthreads();
}

// ---- forward stage 1 (radix-8, NS=1): 4 nonzero inputs from GLOBAL, v[4..7]=0 ----
// NOTE: no trailing barrier — caller supplies the shared one.
__device__ __forceinline__ void stage1_fwd_zero(const float2* gx, float2* out, int t) {
    float2 v0 = gx[t], v1 = gx[t + 256], v2 = gx[t + 512], v3 = gx[t + 768];
    float2 E[4], O[4];
    E[0] = cadd(v0, v2);
    E[2] = csub(v0, v2);
    E[1] = make_float2(v0.x + v2.y, v0.y - v2.x);
    E[3] = make_float2(v0.x - v2.y, v0.y + v2.x);
    O[0] = cadd(v1, v3);
    O[2] = csub(v1, v3);
    O[1] = make_float2(v1.x + v3.y, v1.y - v3.x);
    O[3] = make_float2(v1.x - v3.y, v1.y + v3.x);
    float2 o1, o2, o3;
    omega8<false>(O, o1, o2, o3);
    const int b2 = sbase<1>(t);
    out[b2 ^ 0] = cadd(E[0], O[0]);
    out[b2 ^ 4] = csub(E[0], O[0]);
    out[b2 ^ 1] = cadd(E[1], o1);
    out[b2 ^ 5] = csub(E[1], o1);
    out[b2 ^ 2] = cadd(E[2], o2);
    out[b2 ^ 6] = csub(E[2], o2);
    out[b2 ^ 3] = cadd(E[3], o3);
    out[b2 ^ 7] = csub(E[3], o3);
}

// ---- radix-16 Stockham stage, NS in {8, 128}; 128 active threads ----
// Table twiddles: w^k = T[jm*S*k], S = 1024/(8*NS); inverse = conj multiply.
// HALF=true (inverse final, NS=128): store only outputs k<8 (indices < 1024).
#define R16_STORE(K, WK)                                                          \
    do {                                                                          \
        float2 xa = cadd(E8[K], (WK));                                            \
        if (NS == 128) {                                                          \
            out[(tl ^ (8 * ((K) & 1))) + 128 * (K)] = xa;                         \
            if (!HALF) {                                                          \
                float2 xb = csub(E8[K], (WK));                                    \
                out[(tl ^ (8 * ((K) & 1))) + 128 * ((K) + 8)] = xb;               \
            }                                                                     \
        } else {                                                                  \
            float2 xb = csub(E8[K], (WK));                                        \
            out[IDX(gbase + 8 * (K))]       = xa;                                 \
            out[IDX(gbase + 8 * ((K) + 8))] = xb;                                 \
        }                                                                         \
    } while (0)

template<int NS, bool INV, bool HALF>
__device__ __forceinline__ void stage_r16(const float2* in, float2* out, int t) {
    if (t < 128) {
        const int j  = t;
        const int tl = j ^ ((j >> 4) & 7);       // IDX(j + 128k) == (tl ^ 8(k&1)) + 128k
        const int jm = j & (NS - 1);
        const int js = jm * (1024 / (8 * NS));   // table step (16 for NS=8, 1 for NS=128)
        float2 E8[8], O8[8];
        {   // even inputs k = 2m, twiddle T[js*2m]
            float2 u[8];
            u[0] = in[tl];
#pragma unroll
            for (int m = 1; m < 8; m++) {
                float2 w = __ldg(&g_twtab[js * 2 * m]);
                float2 vv = in[tl + 256 * m];
                u[m] = INV ? cmulc(vv, w) : cmul(vv, w);
            }
            dft8<INV>(u, E8);
        }
        {   // odd inputs k = 2m+1, twiddle T[js*(2m+1)]
            const int tlo = (tl ^ 8) + 128;
            float2 u[8];
#pragma unroll
            for (int m = 0; m < 8; m++) {
                float2 w = __ldg(&g_twtab[js * (2 * m + 1)]);
                float2 vv = in[tlo + 256 * m];
                u[m] = INV ? cmulc(vv, w) : cmul(vv, w);
            }
            dft8<INV>(u, O8);
        }
        const int gbase = (NS == 128) ? 0 : ((((j >> 3) << 7) | jm));
        R16_STORE(0, O8[0]);
        R16_STORE(1, (w16term<1, INV>(O8[1])));
        R16_STORE(2, (w16term<2, INV>(O8[2])));
        R16_STORE(3, (w16term<3, INV>(O8[3])));
        R16_STORE(4, (w16term<4, INV>(O8[4])));
        R16_STORE(5, (w16term<5, INV>(O8[5])));
        R16_STORE(6, (w16term<6, INV>(O8[6])));
        R16_STORE(7, (w16term<7, INV>(O8[7])));
    }
    __syncthreads();
}

// One CTA = one frame, 256 threads.
__global__ __launch_bounds__(256, 4) void yin_fft_kernel(
    const float* __restrict__ x, float* __restrict__ y, int M)
{
    __shared__ float2 bufA[2048];
    __shared__ float2 bufB[2048];
    __shared__ float  ss[2049];
    __shared__ float  warpAgg[8];

    const int t    = threadIdx.x;
    const int lane = t & 31;
    const int wid  = t >> 5;
    const int tld  = t ^ ((t >> 4) & 15);   // == IDX(t)
    const float* xf = x + (size_t)blockIdx.x * FRAME;

    // ---- FUSED: scan1 phase A + stage1 (G -> bufA), sharing ONE barrier ----
    float pr[8];
    float scanv;
    {
        float4 va = ((const float4*)xf)[2 * t];
        float4 vb = ((const float4*)xf)[2 * t + 1];
        float xr[8] = {va.x, va.y, va.z, va.w, vb.x, vb.y, vb.z, vb.w};
        float run = 0.f;
#pragma unroll
        for (int j = 0; j < 8; j++) { run += xr[j] * xr[j]; pr[j] = run; }
        float sc = run;
#pragma unroll
        for (int off = 1; off < 32; off <<= 1) {
            float o = __shfl_up_sync(0xffffffffu, sc, off);
            if (lane >= off) sc += o;
        }
        if (lane == 31) warpAgg[wid] = sc;
        scanv = sc - run;              // exclusive within-warp offset
    }
    stage1_fwd_zero((const float2*)xf, bufA, t);   // no internal barrier
    __syncthreads();                               // covers warpAgg AND bufA

    // ---- scan1 phase B: finish prefix sum of squares -> ss[0..2048] ----
    {
        float wOff = 0.f;
#pragma unroll
        for (int w = 0; w < 8; w++) if (w < wid) wOff += warpAgg[w];
        float tOff = wOff + scanv;
#pragma unroll
        for (int j = 0; j < 8; j++) ss[SSW(8 * t + j + 1)] = tOff + pr[j];
        if (t == 0) ss[SSW(0)] = 0.f;
        // no barrier: ss first read occurs after many stage barriers
    }

    // ---- forward C2C 2048: 3 stages (8 * 16 * 16) ----
    stage_r16<8,   false, false>(bufA, bufB, t);    // A -> B
    stage_r16<128, false, false>(bufB, bufA, t);    // B -> A   (Z in A)

    // ---- FUSED: unpack rfft -> power spectrum -> irfft pack, A -> B ----
    {
#pragma unroll
        for (int i = 0; i < 4; i++) {
            int k = t + 256 * i;                      // k in [0,1024)
            float2 Za = bufA[IDX(k)];
            float2 Zb = bufA[IDX((2048 - k) & 2047)];
            float hex = 0.5f * (Za.x + Zb.x), hey = 0.5f * (Za.y - Zb.y);
            float hox = 0.5f * (Za.y + Zb.y), hoy = -0.5f * (Za.x - Zb.x);
            float s, c;
            sincospif((float)k * (1.0f / 2048.0f), &s, &c);
            float ux = c * hox + s * hoy;
            float uy = c * hoy - s * hox;
            float ax = hex + ux, ay = hey + uy;
            float bx = hex - ux, by = hey - uy;
            float Sk = ax * ax + ay * ay;
            float Sm = bx * bx + by * by;
            float A  = Sk + Sm, dS = Sk - Sm;
            bufB[IDX(k)] = make_float2(0.5f * (A - s * dS), 0.5f * (c * dS));
            if (k > 0)
                bufB[IDX(2048 - k)] = make_float2(0.5f * (A + s * dS), 0.5f * (c * dS));
        }
        if (t == 0) {
            float2 Zn = bufA[IDX(1024)];
            bufB[IDX(1024)] = make_float2(Zn.x * Zn.x + Zn.y * Zn.y, 0.f);
        }
    }
    __syncthreads();

    // ---- inverse C2C 2048: 3 stages; final keeps outputs [0,1024) only ----
    stage_r8<1, true>(bufB, bufA, t, tld);          // B -> A (no twiddle, 256 threads)
    stage_r16<8,   true, false>(bufA, bufB, t);     // A -> B
    stage_r16<128, true, true >(bufB, bufA, t);     // B -> A (half store), r in A

    // ---- d_raw[k] = ss[W-k] + (ss[W]-ss[k]) - 2 r[k] ----
    const int k0 = 8 * t;
    float dr[8];
    {
        float sW = ss[SSW(2048)];
        const float inv = 1.0f / 2048.0f;
        const int rb = (4 * t) ^ ((t >> 2) & 15);     // IDX(4t+q) == rb ^ q
#pragma unroll
        for (int q = 0; q < 4; q++) {
            float2 wv = bufA[rb ^ q];
            float r0 = wv.x * inv, r1 = wv.y * inv;
            int k = k0 + 2 * q;
            dr[2 * q]     = ss[SSW(FRAME - k)]     + (sW - ss[SSW(k)])     - 2.f * r0;
            dr[2 * q + 1] = ss[SSW(FRAME - k - 1)] + (sW - ss[SSW(k + 1)]) - 2.f * r1;
        }
    }
    if (t == 0) dr[0] = 0.f;
    // no barrier: bufB reads finished at last stage's barrier; warpAgg quiet since scan1

    // ---- scan 2: cumsum over lags, normalize -> d0s (reuse bufB, swizzled) ----
    float* d0s = (float*)bufB;
    {
        float run = 0.f;
#pragma unroll
        for (int j = 0; j < 8; j++) { run += dr[j]; pr[j] = run; }
        float ts = run, sc = run;
#pragma unroll
        for (int off = 1; off < 32; off <<= 1) {
            float o = __shfl_up_sync(0xffffffffu, sc, off);
            if (lane >= off) sc += o;
        }
        if (lane == 31) warpAgg[wid] = sc;
        __syncthreads();
        float wOff = 0.f;
#pragma unroll
        for (int w = 0; w < 8; w++) if (w < wid) wOff += warpAgg[w];
        float tOff = wOff + sc - ts;
#pragma unroll
        for (int j = 0; j < 8; j++) {
            int k = k0 + j;
            float cum = tOff + pr[j];
            float val = (float)k * dr[j] / (cum + 1e-7f);
            d0s[SSW(k)] = (k == 0) ? 1.0f : val;
        }
    }
    __syncthreads();

    // ---- epilogue: fractional-lag linear interpolation gather ----
    float* yo = y + (size_t)blockIdx.x * M;
    for (int m = t; m < M; m += 256) {
        float4 p = g_lagpack[m];
        float lag = p.x;
        int fi = __float_as_int(p.y), ci = __float_as_int(p.z);
        float dfl = d0s[SSW(fi)], dce = d0s[SSW(ci)];
        float numer = (lag - (float)fi) * (dce - dfl);
        float denom = (float)(ci - fi);
        yo[m] = numer / denom + dfl;
    }
}

// ---- host-side tables (input-independent; deterministic) ----
static float4 h_lagpack[2048];
static float2 h_twtab[2048];

static inline float bits_to_float(int i) { float f; std::memcpy(&f, &i, 4); return f; }

extern "C" void kernel_launch(void* const* d_in, const int* in_sizes, int n_in,
                              void* d_out, int out_size) {
    const float* x = (const float*)d_in[0];
    int total = in_sizes[0];
    int B = total / FRAME;
    int M = out_size / B;
    int Mc = M < 2048 ? M : 2048;

    for (int m = 0; m < Mc; m++) {
        double midi64 = 5.0 + (double)m * 0.05;
        float  midi32 = (float)midi64;
        double e      = ((double)midi32 - 69.0) / 12.0;
        double lag64  = 22050.0 / (440.0 * exp2(e));
        float  lag32  = (float)lag64;
        int fi = (int)floorf(lag32), ci = (int)ceilf(lag32);
        h_lagpack[m] = make_float4(lag32, bits_to_float(fi), bits_to_float(ci), 0.f);
    }
    const double PI = 3.14159265358979323846;
    for (int n = 0; n < 2048; n++) {
        double a = PI * (double)n / 1024.0;
        h_twtab[n] = make_float2((float)cos(a), (float)(-sin(a)));
    }
    cudaMemcpyToSymbolAsync(g_lagpack, h_lagpack, sizeof(float4) * (size_t)Mc, 0,
                            cudaMemcpyHostToDevice, 0);
    cudaMemcpyToSymbolAsync(g_twtab, h_twtab, sizeof(float2) * 2048, 0,
                            cudaMemcpyHostToDevice, 0);
    yin_fft_kernel<<<B, 256>>>(x, (float*)d_out, M);
}

// round 16
// speedup vs baseline: 1.5111x; 1.5111x over previous
#include <cuda_runtime.h>
#include <cmath>
#include <cstring>

#define FRAME 2048
#define IDX(i) ((i) ^ (((i) >> 4) & 15))   // float2 FFT-buffer swizzle
#define SSW(i) ((i) ^ (((i) >> 5) & 31))   // float scan-array swizzle

// ---- device-global lag table, filled from host via async memcpy-to-symbol ----
__device__ float4 g_lagpack[2048];    // (lag, floor_bits, ceil_bits, 0)

__device__ __forceinline__ float2 cmul(float2 a, float2 b) {
    return make_float2(fmaf(a.x, b.x, -a.y * b.y), fmaf(a.x, b.y, a.y * b.x));
}
__device__ __forceinline__ float2 cadd(float2 a, float2 b) { return make_float2(a.x + b.x, a.y + b.y); }
__device__ __forceinline__ float2 csub(float2 a, float2 b) { return make_float2(a.x - b.x, a.y - b.y); }

template<bool INV>
__device__ __forceinline__ void dft4(float2 a, float2 b, float2 c, float2 d, float2* o) {
    float2 p = cadd(a, c), m = csub(a, c);
    float2 q = cadd(b, d), n = csub(b, d);
    o[0] = cadd(p, q);
    o[2] = csub(p, q);
    if (!INV) { o[1] = make_float2(m.x + n.y, m.y - n.x); o[3] = make_float2(m.x - n.y, m.y + n.x); }
    else      { o[1] = make_float2(m.x - n.y, m.y + n.x); o[3] = make_float2(m.x + n.y, m.y - n.x); }
}

template<bool INV>
__device__ __forceinline__ void omega8(const float2* O, float2& o1, float2& o2, float2& o3) {
    const float s2 = 0.70710678118654752f;
    if (!INV) {
        o1 = make_float2(s2 * (O[1].x + O[1].y), s2 * (O[1].y - O[1].x));
        o2 = make_float2(O[2].y, -O[2].x);
        o3 = make_float2(s2 * (O[3].y - O[3].x), -s2 * (O[3].x + O[3].y));
    } else {
        o1 = make_float2(s2 * (O[1].x - O[1].y), s2 * (O[1].y + O[1].x));
        o2 = make_float2(-O[2].y, O[2].x);
        o3 = make_float2(-s2 * (O[3].x + O[3].y), s2 * (O[3].x - O[3].y));
    }
}

// full DFT-8, natural-order outputs
template<bool INV>
__device__ __forceinline__ void dft8(const float2* u, float2* X) {
    float2 E[4], O[4];
    dft4<INV>(u[0], u[2], u[4], u[6], E);
    dft4<INV>(u[1], u[3], u[5], u[7], O);
    float2 o1, o2, o3;
    omega8<INV>(O, o1, o2, o3);
    X[0] = cadd(E[0], O[0]); X[4] = csub(E[0], O[0]);
    X[1] = cadd(E[1], o1);   X[5] = csub(E[1], o1);
    X[2] = cadd(E[2], o2);   X[6] = csub(E[2], o2);
    X[3] = cadd(E[3], o3);   X[7] = csub(E[3], o3);
}

// ω16^K * o (K = 1..7 compile-time), conjugated for inverse
template<int K, bool INV>
__device__ __forceinline__ float2 w16term(float2 o) {
    const float c8 = 0.92387953251128674f;
    const float s8 = 0.38268343236508978f;
    const float s2 = 0.70710678118654752f;
    const float sg = INV ? 1.f : -1.f;
    if (K == 4) return INV ? make_float2(-o.y, o.x) : make_float2(o.y, -o.x);
    float2 w;
    if (K == 1) w = make_float2( c8, sg * s8);
    if (K == 2) w = make_float2( s2, sg * s2);
    if (K == 3) w = make_float2( s8, sg * c8);
    if (K == 5) w = make_float2(-s8, sg * c8);
    if (K == 6) w = make_float2(-s2, sg * s2);
    if (K == 7) w = make_float2(-c8, sg * s8);
    return cmul(o, w);
}

// compile-time store-offset constant (NS=1 used by radix-8 stages)
template<int NS>
__device__ __forceinline__ constexpr int soff(int m) {
    return NS == 1 ? m
         : NS == 8 ? ((m << 3) | ((m >> 1) & 3))
                   : ((m << 6) | ((m & 3) << 2));
}
template<int NS>
__device__ __forceinline__ int sbase(int t) {
    if (NS == 1)  return (8 * t) ^ ((t >> 1) & 15);
    if (NS == 8)  return (((t >> 3) << 6) | (t & 7)) ^ (((t >> 3) & 3) << 2);
    /* NS == 64 */ return (((t >> 6) << 9) | (t & 63)) ^ ((t >> 4) & 3);
}

// ---- generic radix-8 Stockham stage (smem -> smem); used for inverse NS=1 ----
template<int NS, bool INV>
__device__ __forceinline__ void stage_r8(const float2* in, float2* out, int t, int tld) {
    float2 v[8];
#pragma unroll
    for (int k = 0; k < 8; k++) v[k] = in[tld + 256 * k];
    if (NS > 1) {
        const int jm = t & (NS - 1);
        float s, c;
        sincospif((float)jm * (1.0f / (4.0f * NS)), &s, &c);
        if (!INV) s = -s;
        float2 w1 = make_float2(c, s);
        v[1] = cmul(v[1], w1);
        float2 w2 = cmul(w1, w1);
        v[2] = cmul(v[2], w2);
        float2 w3 = cmul(w2, w1);
        v[3] = cmul(v[3], w3);
        float2 w4 = cmul(w2, w2);
        v[4] = cmul(v[4], w4);
        v[5] = cmul(v[5], cmul(w4, w1));
        v[6] = cmul(v[6], cmul(w4, w2));
        v[7] = cmul(v[7], cmul(w4, w3));
    }
    float2 X[8];
    dft8<INV>(v, X);
    const int b2 = sbase<NS>(t);
    out[b2 ^ soff<NS>(0)] = X[0];
    out[b2 ^ soff<NS>(4)] = X[4];
    out[b2 ^ soff<NS>(1)] = X[1];
    out[b2 ^ soff<NS>(5)] = X[5];
    out[b2 ^ soff<NS>(2)] = X[2];
    out[b2 ^ soff<NS>(6)] = X[6];
    out[b2 ^ soff<NS>(3)] = X[3];
    out[b2 ^ soff<NS>(7)] = X[7];
    __syncthreads();
}

// ---- forward stage 1 (radix-8, NS=1): 4 nonzero inputs from GLOBAL, v[4..7]=0 ----
// NOTE: no trailing barrier — caller supplies the shared one.
__device__ __forceinline__ void stage1_fwd_zero(const float2* gx, float2* out, int t) {
    float2 v0 = gx[t], v1 = gx[t + 256], v2 = gx[t + 512], v3 = gx[t + 768];
    float2 E[4], O[4];
    E[0] = cadd(v0, v2);
    E[2] = csub(v0, v2);
    E[1] = make_float2(v0.x + v2.y, v0.y - v2.x);
    E[3] = make_float2(v0.x - v2.y, v0.y + v2.x);
    O[0] = cadd(v1, v3);
    O[2] = csub(v1, v3);
    O[1] = make_float2(v1.x + v3.y, v1.y - v3.x);
    O[3] = make_float2(v1.x - v3.y, v1.y + v3.x);
    float2 o1, o2, o3;
    omega8<false>(O, o1, o2, o3);
    const int b2 = sbase<1>(t);
    out[b2 ^ 0] = cadd(E[0], O[0]);
    out[b2 ^ 4] = csub(E[0], O[0]);
    out[b2 ^ 1] = cadd(E[1], o1);
    out[b2 ^ 5] = csub(E[1], o1);
    out[b2 ^ 2] = cadd(E[2], o2);
    out[b2 ^ 6] = csub(E[2], o2);
    out[b2 ^ 3] = cadd(E[3], o3);
    out[b2 ^ 7] = csub(E[3], o3);
}

// ---- radix-16 Stockham stage, NS in {8, 128}; 128 active threads ----
// Even/odd DFT-8 split with sequential twiddle chain to keep liveness low.
// HALF=true (inverse final, NS=128): store only outputs k<8 (indices < 1024).
#define R16_STORE(K, WK)                                                          \
    do {                                                                          \
        float2 xa = cadd(E8[K], (WK));                                            \
        if (NS == 128) {                                                          \
            out[(tl ^ (8 * ((K) & 1))) + 128 * (K)] = xa;                         \
            if (!HALF) {                                                          \
                float2 xb = csub(E8[K], (WK));                                    \
                out[(tl ^ (8 * ((K) & 1))) + 128 * ((K) + 8)] = xb;               \
            }                                                                     \
        } else {                                                                  \
            float2 xb = csub(E8[K], (WK));                                        \
            out[IDX(gbase + 8 * (K))]       = xa;                                 \
            out[IDX(gbase + 8 * ((K) + 8))] = xb;                                 \
        }                                                                         \
    } while (0)

template<int NS, bool INV, bool HALF>
__device__ __forceinline__ void stage_r16(const float2* in, float2* out, int t) {
    if (t < 128) {
        const int j  = t;
        const int tl = j ^ ((j >> 4) & 7);       // IDX(j + 128k) == (tl ^ 8(k&1)) + 128k
        const int jm = j & (NS - 1);
        float s, c;
        sincospif((float)jm * (1.0f / (8.0f * NS)), &s, &c);
        if (!INV) s = -s;
        const float2 w1 = make_float2(c, s);
        const float2 W  = cmul(w1, w1);          // w^2
        float2 E8[8], O8[8];
        {   // even inputs k = 2m, twiddle w^(2m) = W^m
            float2 u[8];
            u[0] = in[tl];
            float2 acc = W;
#pragma unroll
            for (int m = 1; m < 8; m++) {
                u[m] = cmul(in[tl + 256 * m], acc);
                if (m < 7) acc = cmul(acc, W);
            }
            dft8<INV>(u, E8);
        }
        {   // odd inputs k = 2m+1, twiddle w^(2m+1) = w * W^m
            const int tlo = (tl ^ 8) + 128;
            float2 u[8];
            float2 acc = w1;
            u[0] = cmul(in[tlo], acc);
#pragma unroll
            for (int m = 1; m < 8; m++) {
                acc = cmul(acc, W);
                u[m] = cmul(in[tlo + 256 * m], acc);
            }
            dft8<INV>(u, O8);
        }
        const int gbase = (NS == 128) ? 0 : ((((j >> 3) << 7) | jm));
        R16_STORE(0, O8[0]);
        R16_STORE(1, (w16term<1, INV>(O8[1])));
        R16_STORE(2, (w16term<2, INV>(O8[2])));
        R16_STORE(3, (w16term<3, INV>(O8[3])));
        R16_STORE(4, (w16term<4, INV>(O8[4])));
        R16_STORE(5, (w16term<5, INV>(O8[5])));
        R16_STORE(6, (w16term<6, INV>(O8[6])));
        R16_STORE(7, (w16term<7, INV>(O8[7])));
    }
    __syncthreads();
}

// One CTA = one frame, 256 threads. Occupancy experiment: 5 CTAs/SM (51-reg cap).
__global__ __launch_bounds__(256, 5) void yin_fft_kernel(
    const float* __restrict__ x, float* __restrict__ y, int M)
{
    __shared__ float2 bufA[2048];
    __shared__ float2 bufB[2048];
    __shared__ float  ss[2049];
    __shared__ float  warpAgg[8];

    const int t    = threadIdx.x;
    const int lane = t & 31;
    const int wid  = t >> 5;
    const int tld  = t ^ ((t >> 4) & 15);   // == IDX(t)
    const float* xf = x + (size_t)blockIdx.x * FRAME;

    // ---- FUSED: scan1 phase A + stage1 (G -> bufA), sharing ONE barrier ----
    float pr[8];
    float scanv;
    {
        float4 va = ((const float4*)xf)[2 * t];
        float4 vb = ((const float4*)xf)[2 * t + 1];
        float xr[8] = {va.x, va.y, va.z, va.w, vb.x, vb.y, vb.z, vb.w};
        float run = 0.f;
#pragma unroll
        for (int j = 0; j < 8; j++) { run += xr[j] * xr[j]; pr[j] = run; }
        float sc = run;
#pragma unroll
        for (int off = 1; off < 32; off <<= 1) {
            float o = __shfl_up_sync(0xffffffffu, sc, off);
            if (lane >= off) sc += o;
        }
        if (lane == 31) warpAgg[wid] = sc;
        scanv = sc - run;              // exclusive within-warp offset
    }
    stage1_fwd_zero((const float2*)xf, bufA, t);   // no internal barrier
    __syncthreads();                               // covers warpAgg AND bufA

    // ---- scan1 phase B: finish prefix sum of squares -> ss[0..2048] ----
    {
        float wOff = 0.f;
#pragma unroll
        for (int w = 0; w < 8; w++) if (w < wid) wOff += warpAgg[w];
        float tOff = wOff + scanv;
#pragma unroll
        for (int j = 0; j < 8; j++) ss[SSW(8 * t + j + 1)] = tOff + pr[j];
        if (t == 0) ss[SSW(0)] = 0.f;
        // no barrier: ss first read occurs after many stage barriers
    }

    // ---- forward C2C 2048: 3 stages (8 * 16 * 16) ----
    stage_r16<8,   false, false>(bufA, bufB, t);    // A -> B
    stage_r16<128, false, false>(bufB, bufA, t);    // B -> A   (Z in A)

    // ---- FUSED: unpack rfft -> power spectrum -> irfft pack, A -> B ----
    {
#pragma unroll
        for (int i = 0; i < 4; i++) {
            int k = t + 256 * i;                      // k in [0,1024)
            float2 Za = bufA[IDX(k)];
            float2 Zb = bufA[IDX((2048 - k) & 2047)];
            float hex = 0.5f * (Za.x + Zb.x), hey = 0.5f * (Za.y - Zb.y);
            float hox = 0.5f * (Za.y + Zb.y), hoy = -0.5f * (Za.x - Zb.x);
            float s, c;
            sincospif((float)k * (1.0f / 2048.0f), &s, &c);
            float ux = c * hox + s * hoy;
            float uy = c * hoy - s * hox;
            float ax = hex + ux, ay = hey + uy;
            float bx = hex - ux, by = hey - uy;
            float Sk = ax * ax + ay * ay;
            float Sm = bx * bx + by * by;
            float A  = Sk + Sm, dS = Sk - Sm;
            bufB[IDX(k)] = make_float2(0.5f * (A - s * dS), 0.5f * (c * dS));
            if (k > 0)
                bufB[IDX(2048 - k)] = make_float2(0.5f * (A + s * dS), 0.5f * (c * dS));
        }
        if (t == 0) {
            float2 Zn = bufA[IDX(1024)];
            bufB[IDX(1024)] = make_float2(Zn.x * Zn.x + Zn.y * Zn.y, 0.f);
        }
    }
    __syncthreads();

    // ---- inverse C2C 2048: 3 stages; final keeps outputs [0,1024) only ----
    stage_r8<1, true>(bufB, bufA, t, tld);          // B -> A (no twiddle, 256 threads)
    stage_r16<8,   true, false>(bufA, bufB, t);     // A -> B
    stage_r16<128, true, true >(bufB, bufA, t);     // B -> A (half store), r in A

    // ---- d_raw[k] = ss[W-k] + (ss[W]-ss[k]) - 2 r[k] ----
    const int k0 = 8 * t;
    float dr[8];
    {
        float sW = ss[SSW(2048)];
        const float inv = 1.0f / 2048.0f;
        const int rb = (4 * t) ^ ((t >> 2) & 15);     // IDX(4t+q) == rb ^ q
#pragma unroll
        for (int q = 0; q < 4; q++) {
            float2 wv = bufA[rb ^ q];
            float r0 = wv.x * inv, r1 = wv.y * inv;
            int k = k0 + 2 * q;
            dr[2 * q]     = ss[SSW(FRAME - k)]     + (sW - ss[SSW(k)])     - 2.f * r0;
            dr[2 * q + 1] = ss[SSW(FRAME - k - 1)] + (sW - ss[SSW(k + 1)]) - 2.f * r1;
        }
    }
    if (t == 0) dr[0] = 0.f;
    // no barrier: bufB reads finished at last stage's barrier; warpAgg quiet since scan1

    // ---- scan 2: cumsum over lags, normalize -> d0s (reuse bufB, swizzled) ----
    float* d0s = (float*)bufB;
    {
        float run = 0.f;
#pragma unroll
        for (int j = 0; j < 8; j++) { run += dr[j]; pr[j] = run; }
        float ts = run, sc = run;
#pragma unroll
        for (int off = 1; off < 32; off <<= 1) {
            float o = __shfl_up_sync(0xffffffffu, sc, off);
            if (lane >= off) sc += o;
        }
        if (lane == 31) warpAgg[wid] = sc;
        __syncthreads();
        float wOff = 0.f;
#pragma unroll
        for (int w = 0; w < 8; w++) if (w < wid) wOff += warpAgg[w];
        float tOff = wOff + sc - ts;
#pragma unroll
        for (int j = 0; j < 8; j++) {
            int k = k0 + j;
            float cum = tOff + pr[j];
            float val = (float)k * dr[j] / (cum + 1e-7f);
            d0s[SSW(k)] = (k == 0) ? 1.0f : val;
        }
    }
    __syncthreads();

    // ---- epilogue: fractional-lag linear interpolation gather ----
    float* yo = y + (size_t)blockIdx.x * M;
    for (int m = t; m < M; m += 256) {
        float4 p = g_lagpack[m];
        float lag = p.x;
        int fi = __float_as_int(p.y), ci = __float_as_int(p.z);
        float dfl = d0s[SSW(fi)], dce = d0s[SSW(ci)];
        float numer = (lag - (float)fi) * (dce - dfl);
        float denom = (float)(ci - fi);
        yo[m] = numer / denom + dfl;
    }
}

// ---- host-side lag table (input-independent; deterministic) ----
static float4 h_lagpack[2048];

static inline float bits_to_float(int i) { float f; std::memcpy(&f, &i, 4); return f; }

extern "C" void kernel_launch(void* const* d_in, const int* in_sizes, int n_in,
                              void* d_out, int out_size) {
    const float* x = (const float*)d_in[0];
    int total = in_sizes[0];
    int B = total / FRAME;
    int M = out_size / B;
    int Mc = M < 2048 ? M : 2048;

    for (int m = 0; m < Mc; m++) {
        double midi64 = 5.0 + (double)m * 0.05;
        float  midi32 = (float)midi64;
        double e      = ((double)midi32 - 69.0) / 12.0;
        double lag64  = 22050.0 / (440.0 * exp2(e));
        float  lag32  = (float)lag64;
        int fi = (int)floorf(lag32), ci = (int)ceilf(lag32);
        h_lagpack[m] = make_float4(lag32, bits_to_float(fi), bits_to_float(ci), 0.f);
    }
    cudaMemcpyToSymbolAsync(g_lagpack, h_lagpack, sizeof(float4) * (size_t)Mc, 0,
                            cudaMemcpyHostToDevice, 0);
    yin_fft_kernel<<<B, 256>>>(x, (float*)d_out, M);
}

// round 17
// speedup vs baseline: 1.5962x; 1.0563x over previous
#include <cuda_runtime.h>
#include <cmath>
#include <cstring>

#define FRAME 2048
#define IDX(i) ((i) ^ (((i) >> 4) & 15))   // float2 FFT-buffer swizzle
#define SSW(i) ((i) ^ (((i) >> 5) & 31))   // float scan-array swizzle

// ---- device-global lag table, filled from host via async memcpy-to-symbol ----
__device__ float4 g_lagpack[2048];    // (lag, floor_bits, ceil_bits, 0)

__device__ __forceinline__ float2 cmul(float2 a, float2 b) {
    return make_float2(fmaf(a.x, b.x, -a.y * b.y), fmaf(a.x, b.y, a.y * b.x));
}
__device__ __forceinline__ float2 cadd(float2 a, float2 b) { return make_float2(a.x + b.x, a.y + b.y); }
__device__ __forceinline__ float2 csub(float2 a, float2 b) { return make_float2(a.x - b.x, a.y - b.y); }

template<bool INV>
__device__ __forceinline__ void dft4(float2 a, float2 b, float2 c, float2 d, float2* o) {
    float2 p = cadd(a, c), m = csub(a, c);
    float2 q = cadd(b, d), n = csub(b, d);
    o[0] = cadd(p, q);
    o[2] = csub(p, q);
    if (!INV) { o[1] = make_float2(m.x + n.y, m.y - n.x); o[3] = make_float2(m.x - n.y, m.y + n.x); }
    else      { o[1] = make_float2(m.x - n.y, m.y + n.x); o[3] = make_float2(m.x + n.y, m.y - n.x); }
}

template<bool INV>
__device__ __forceinline__ void omega8(const float2* O, float2& o1, float2& o2, float2& o3) {
    const float s2 = 0.70710678118654752f;
    if (!INV) {
        o1 = make_float2(s2 * (O[1].x + O[1].y), s2 * (O[1].y - O[1].x));
        o2 = make_float2(O[2].y, -O[2].x);
        o3 = make_float2(s2 * (O[3].y - O[3].x), -s2 * (O[3].x + O[3].y));
    } else {
        o1 = make_float2(s2 * (O[1].x - O[1].y), s2 * (O[1].y + O[1].x));
        o2 = make_float2(-O[2].y, O[2].x);
        o3 = make_float2(-s2 * (O[3].x + O[3].y), s2 * (O[3].x - O[3].y));
    }
}

// full DFT-8, natural-order outputs
template<bool INV>
__device__ __forceinline__ void dft8(const float2* u, float2* X) {
    float2 E[4], O[4];
    dft4<INV>(u[0], u[2], u[4], u[6], E);
    dft4<INV>(u[1], u[3], u[5], u[7], O);
    float2 o1, o2, o3;
    omega8<INV>(O, o1, o2, o3);
    X[0] = cadd(E[0], O[0]); X[4] = csub(E[0], O[0]);
    X[1] = cadd(E[1], o1);   X[5] = csub(E[1], o1);
    X[2] = cadd(E[2], o2);   X[6] = csub(E[2], o2);
    X[3] = cadd(E[3], o3);   X[7] = csub(E[3], o3);
}

// ω16^K * o (K = 1..7 compile-time), conjugated for inverse
template<int K, bool INV>
__device__ __forceinline__ float2 w16term(float2 o) {
    const float c8 = 0.92387953251128674f;
    const float s8 = 0.38268343236508978f;
    const float s2 = 0.70710678118654752f;
    const float sg = INV ? 1.f : -1.f;
    if (K == 4) return INV ? make_float2(-o.y, o.x) : make_float2(o.y, -o.x);
    float2 w;
    if (K == 1) w = make_float2( c8, sg * s8);
    if (K == 2) w = make_float2( s2, sg * s2);
    if (K == 3) w = make_float2( s8, sg * c8);
    if (K == 5) w = make_float2(-s8, sg * c8);
    if (K == 6) w = make_float2(-s2, sg * s2);
    if (K == 7) w = make_float2(-c8, sg * s8);
    return cmul(o, w);
}

// compile-time store-offset constant (NS=1 used by radix-8 stages)
template<int NS>
__device__ __forceinline__ constexpr int soff(int m) {
    return NS == 1 ? m
         : NS == 8 ? ((m << 3) | ((m >> 1) & 3))
                   : ((m << 6) | ((m & 3) << 2));
}
template<int NS>
__device__ __forceinline__ int sbase(int t) {
    if (NS == 1)  return (8 * t) ^ ((t >> 1) & 15);
    if (NS == 8)  return (((t >> 3) << 6) | (t & 7)) ^ (((t >> 3) & 3) << 2);
    /* NS == 64 */ return (((t >> 6) << 9) | (t & 63)) ^ ((t >> 4) & 3);
}

// ---- generic radix-8 Stockham stage (smem -> smem); used for inverse NS=1 ----
template<int NS, bool INV>
__device__ __forceinline__ void stage_r8(const float2* in, float2* out, int t, int tld) {
    float2 v[8];
#pragma unroll
    for (int k = 0; k < 8; k++) v[k] = in[tld + 256 * k];
    if (NS > 1) {
        const int jm = t & (NS - 1);
        float s, c;
        sincospif((float)jm * (1.0f / (4.0f * NS)), &s, &c);
        if (!INV) s = -s;
        float2 w1 = make_float2(c, s);
        v[1] = cmul(v[1], w1);
        float2 w2 = cmul(w1, w1);
        v[2] = cmul(v[2], w2);
        float2 w3 = cmul(w2, w1);
        v[3] = cmul(v[3], w3);
        float2 w4 = cmul(w2, w2);
        v[4] = cmul(v[4], w4);
        v[5] = cmul(v[5], cmul(w4, w1));
        v[6] = cmul(v[6], cmul(w4, w2));
        v[7] = cmul(v[7], cmul(w4, w3));
    }
    float2 X[8];
    dft8<INV>(v, X);
    const int b2 = sbase<NS>(t);
    out[b2 ^ soff<NS>(0)] = X[0];
    out[b2 ^ soff<NS>(4)] = X[4];
    out[b2 ^ soff<NS>(1)] = X[1];
    out[b2 ^ soff<NS>(5)] = X[5];
    out[b2 ^ soff<NS>(2)] = X[2];
    out[b2 ^ soff<NS>(6)] = X[6];
    out[b2 ^ soff<NS>(3)] = X[3];
    out[b2 ^ soff<NS>(7)] = X[7];
    __syncthreads();
}

// ---- forward stage 1 (radix-8, NS=1): 4 nonzero inputs from GLOBAL, v[4..7]=0 ----
// NOTE: no trailing barrier — caller supplies the shared one.
__device__ __forceinline__ void stage1_fwd_zero(const float2* gx, float2* out, int t) {
    float2 v0 = gx[t], v1 = gx[t + 256], v2 = gx[t + 512], v3 = gx[t + 768];
    float2 E[4], O[4];
    E[0] = cadd(v0, v2);
    E[2] = csub(v0, v2);
    E[1] = make_float2(v0.x + v2.y, v0.y - v2.x);
    E[3] = make_float2(v0.x - v2.y, v0.y + v2.x);
    O[0] = cadd(v1, v3);
    O[2] = csub(v1, v3);
    O[1] = make_float2(v1.x + v3.y, v1.y - v3.x);
    O[3] = make_float2(v1.x - v3.y, v1.y + v3.x);
    float2 o1, o2, o3;
    omega8<false>(O, o1, o2, o3);
    const int b2 = sbase<1>(t);
    out[b2 ^ 0] = cadd(E[0], O[0]);
    out[b2 ^ 4] = csub(E[0], O[0]);
    out[b2 ^ 1] = cadd(E[1], o1);
    out[b2 ^ 5] = csub(E[1], o1);
    out[b2 ^ 2] = cadd(E[2], o2);
    out[b2 ^ 6] = csub(E[2], o2);
    out[b2 ^ 3] = cadd(E[3], o3);
    out[b2 ^ 7] = csub(E[3], o3);
}

// ---- radix-16 Stockham stage, NS in {8, 128}; 128 active threads ----
// Twiddle seed w1 from per-CTA smem table (forward-signed); inverse takes conj.
// HALF=true (inverse final, NS=128): store only outputs k<8 (indices < 1024).
#define R16_STORE(K, WK)                                                          \
    do {                                                                          \
        float2 xa = cadd(E8[K], (WK));                                            \
        if (NS == 128) {                                                          \
            out[(tl ^ (8 * ((K) & 1))) + 128 * (K)] = xa;                         \
            if (!HALF) {                                                          \
                float2 xb = csub(E8[K], (WK));                                    \
                out[(tl ^ (8 * ((K) & 1))) + 128 * ((K) + 8)] = xb;               \
            }                                                                     \
        } else {                                                                  \
            float2 xb = csub(E8[K], (WK));                                        \
            out[IDX(gbase + 8 * (K))]       = xa;                                 \
            out[IDX(gbase + 8 * ((K) + 8))] = xb;                                 \
        }                                                                         \
    } while (0)

template<int NS, bool INV, bool HALF>
__device__ __forceinline__ void stage_r16(const float2* in, float2* out, int t,
                                          const float2* tws) {
    if (t < 128) {
        const int j  = t;
        const int tl = j ^ ((j >> 4) & 7);       // IDX(j + 128k) == (tl ^ 8(k&1)) + 128k
        const int jm = j & (NS - 1);
        const float2 wt = tws[(NS == 8) ? (128 + jm) : jm];   // e^{-i pi jm/(8NS)}
        const float2 w1 = INV ? make_float2(wt.x, -wt.y) : wt;
        const float2 W  = cmul(w1, w1);          // w^2
        float2 E8[8], O8[8];
        {   // even inputs k = 2m, twiddle w^(2m) = W^m
            float2 u[8];
            u[0] = in[tl];
            float2 acc = W;
#pragma unroll
            for (int m = 1; m < 8; m++) {
                u[m] = cmul(in[tl + 256 * m], acc);
                if (m < 7) acc = cmul(acc, W);
            }
            dft8<INV>(u, E8);
        }
        {   // odd inputs k = 2m+1, twiddle w^(2m+1) = w * W^m
            const int tlo = (tl ^ 8) + 128;
            float2 u[8];
            float2 acc = w1;
            u[0] = cmul(in[tlo], acc);
#pragma unroll
            for (int m = 1; m < 8; m++) {
                acc = cmul(acc, W);
                u[m] = cmul(in[tlo + 256 * m], acc);
            }
            dft8<INV>(u, O8);
        }
        const int gbase = (NS == 128) ? 0 : ((((j >> 3) << 7) | jm));
        R16_STORE(0, O8[0]);
        R16_STORE(1, (w16term<1, INV>(O8[1])));
        R16_STORE(2, (w16term<2, INV>(O8[2])));
        R16_STORE(3, (w16term<3, INV>(O8[3])));
        R16_STORE(4, (w16term<4, INV>(O8[4])));
        R16_STORE(5, (w16term<5, INV>(O8[5])));
        R16_STORE(6, (w16term<6, INV>(O8[6])));
        R16_STORE(7, (w16term<7, INV>(O8[7])));
    }
    __syncthreads();
}

// One CTA = one frame, 256 threads.
__global__ __launch_bounds__(256, 4) void yin_fft_kernel(
    const float* __restrict__ x, float* __restrict__ y, int M)
{
    __shared__ float2 bufA[2048];
    __shared__ float2 bufB[2048];
    __shared__ float  ss[2049];
    __shared__ float  warpAgg[8];
    __shared__ float2 twsm[136];   // [0..127]: e^{-i pi j/1024}; [128..135]: e^{-i pi j/64}

    const int t    = threadIdx.x;
    const int lane = t & 31;
    const int wid  = t >> 5;
    const int tld  = t ^ ((t >> 4) & 15);   // == IDX(t)
    const float* xf = x + (size_t)blockIdx.x * FRAME;

    // ---- FUSED: scan1 phase A + twiddle-table fill + stage1 (G -> bufA),
    //      all covered by ONE barrier ----
    float pr[8];
    float scanv;
    {
        float4 va = ((const float4*)xf)[2 * t];
        float4 vb = ((const float4*)xf)[2 * t + 1];
        float xr[8] = {va.x, va.y, va.z, va.w, vb.x, vb.y, vb.z, vb.w};
        float run = 0.f;
#pragma unroll
        for (int j = 0; j < 8; j++) { run += xr[j] * xr[j]; pr[j] = run; }
        float sc = run;
#pragma unroll
        for (int off = 1; off < 32; off <<= 1) {
            float o = __shfl_up_sync(0xffffffffu, sc, off);
            if (lane >= off) sc += o;
        }
        if (lane == 31) warpAgg[wid] = sc;
        scanv = sc - run;              // exclusive within-warp offset
    }
    if (t < 136) {
        float s, c;
        if (t < 128) sincospif((float)t * (1.0f / 1024.0f), &s, &c);
        else         sincospif((float)(t - 128) * (1.0f / 64.0f), &s, &c);
        twsm[t] = make_float2(c, -s);
    }
    stage1_fwd_zero((const float2*)xf, bufA, t);   // no internal barrier
    __syncthreads();                               // covers warpAgg, twsm AND bufA

    // ---- scan1 phase B: finish prefix sum of squares -> ss[0..2048] ----
    {
        float wOff = 0.f;
#pragma unroll
        for (int w = 0; w < 8; w++) if (w < wid) wOff += warpAgg[w];
        float tOff = wOff + scanv;
#pragma unroll
        for (int j = 0; j < 8; j++) ss[SSW(8 * t + j + 1)] = tOff + pr[j];
        if (t == 0) ss[SSW(0)] = 0.f;
        // no barrier: ss first read occurs after many stage barriers
    }

    // ---- forward C2C 2048: 3 stages (8 * 16 * 16) ----
    stage_r16<8,   false, false>(bufA, bufB, t, twsm);    // A -> B
    stage_r16<128, false, false>(bufB, bufA, t, twsm);    // B -> A   (Z in A)

    // ---- FUSED: unpack rfft -> power spectrum -> irfft pack, A -> B ----
    {
        float s0, c0;
        sincospif((float)t * (1.0f / 2048.0f), &s0, &c0);
        float2 wv = make_float2(c0, s0);                          // e^{i pi t/2048}
        const float2 C8 = make_float2(0.92387953251128674f,
                                      0.38268343236508978f);      // e^{i pi/8}
#pragma unroll
        for (int i = 0; i < 4; i++) {
            int k = t + 256 * i;                      // k in [0,1024)
            float2 Za = bufA[IDX(k)];
            float2 Zb = bufA[IDX((2048 - k) & 2047)];
            float hex = 0.5f * (Za.x + Zb.x), hey = 0.5f * (Za.y - Zb.y);
            float hox = 0.5f * (Za.y + Zb.y), hoy = -0.5f * (Za.x - Zb.x);
            float c = wv.x, s = wv.y;
            float ux = c * hox + s * hoy;
            float uy = c * hoy - s * hox;
            float ax = hex + ux, ay = hey + uy;
            float bx = hex - ux, by = hey - uy;
            float Sk = ax * ax + ay * ay;
            float Sm = bx * bx + by * by;
            float A  = Sk + Sm, dS = Sk - Sm;
            bufB[IDX(k)] = make_float2(0.5f * (A - s * dS), 0.5f * (c * dS));
            if (k > 0)
                bufB[IDX(2048 - k)] = make_float2(0.5f * (A + s * dS), 0.5f * (c * dS));
            wv = cmul(wv, C8);                        // advance k by 256
        }
        if (t == 0) {
            float2 Zn = bufA[IDX(1024)];
            bufB[IDX(1024)] = make_float2(Zn.x * Zn.x + Zn.y * Zn.y, 0.f);
        }
    }
    __syncthreads();

    // ---- inverse C2C 2048: 3 stages; final keeps outputs [0,1024) only ----
    stage_r8<1, true>(bufB, bufA, t, tld);                // B -> A (no twiddle, 256 thr)
    stage_r16<8,   true, false>(bufA, bufB, t, twsm);     // A -> B
    stage_r16<128, true, true >(bufB, bufA, t, twsm);     // B -> A (half store), r in A

    // ---- d_raw[k] = ss[W-k] + (ss[W]-ss[k]) - 2 r[k] ----
    const int k0 = 8 * t;
    float dr[8];
    {
        float sW = ss[SSW(2048)];
        const float inv = 1.0f / 2048.0f;
        const int rb = (4 * t) ^ ((t >> 2) & 15);     // IDX(4t+q) == rb ^ q
#pragma unroll
        for (int q = 0; q < 4; q++) {
            float2 wv = bufA[rb ^ q];
            float r0 = wv.x * inv, r1 = wv.y * inv;
            int k = k0 + 2 * q;
            dr[2 * q]     = ss[SSW(FRAME - k)]     + (sW - ss[SSW(k)])     - 2.f * r0;
            dr[2 * q + 1] = ss[SSW(FRAME - k - 1)] + (sW - ss[SSW(k + 1)]) - 2.f * r1;
        }
    }
    if (t == 0) dr[0] = 0.f;
    // no barrier: bufB reads finished at last stage's barrier; warpAgg quiet since scan1

    // ---- scan 2: cumsum over lags, normalize -> d0s (reuse bufB, swizzled) ----
    float* d0s = (float*)bufB;
    {
        float run = 0.f;
#pragma unroll
        for (int j = 0; j < 8; j++) { run += dr[j]; pr[j] = run; }
        float ts = run, sc = run;
#pragma unroll
        for (int off = 1; off < 32; off <<= 1) {
            float o = __shfl_up_sync(0xffffffffu, sc, off);
            if (lane >= off) sc += o;
        }
        if (lane == 31) warpAgg[wid] = sc;
        __syncthreads();
        float wOff = 0.f;
#pragma unroll
        for (int w = 0; w < 8; w++) if (w < wid) wOff += warpAgg[w];
        float tOff = wOff + sc - ts;
#pragma unroll
        for (int j = 0; j < 8; j++) {
            int k = k0 + j;
            float cum = tOff + pr[j];
            float val = (float)k * dr[j] / (cum + 1e-7f);
            d0s[SSW(k)] = (k == 0) ? 1.0f : val;
        }
    }
    __syncthreads();

    // ---- epilogue: fractional-lag linear interpolation gather ----
    float* yo = y + (size_t)blockIdx.x * M;
    for (int m = t; m < M; m += 256) {
        float4 p = g_lagpack[m];
        float lag = p.x;
        int fi = __float_as_int(p.y), ci = __float_as_int(p.z);
        float dfl = d0s[SSW(fi)], dce = d0s[SSW(ci)];
        float numer = (lag - (float)fi) * (dce - dfl);
        float denom = (float)(ci - fi);
        yo[m] = numer / denom + dfl;
    }
}

// ---- host-side lag table (input-independent; deterministic) ----
static float4 h_lagpack[2048];

static inline float bits_to_float(int i) { float f; std::memcpy(&f, &i, 4); return f; }

extern "C" void kernel_launch(void* const* d_in, const int* in_sizes, int n_in,
                              void* d_out, int out_size) {
    const float* x = (const float*)d_in[0];
    int total = in_sizes[0];
    int B = total / FRAME;
    int M = out_size / B;
    int Mc = M < 2048 ? M : 2048;

    for (int m = 0; m < Mc; m++) {
        double midi64 = 5.0 + (double)m * 0.05;
        float  midi32 = (float)midi64;
        double e      = ((double)midi32 - 69.0) / 12.0;
        double lag64  = 22050.0 / (440.0 * exp2(e));
        float  lag32  = (float)lag64;
        int fi = (int)floorf(lag32), ci = (int)ceilf(lag32);
        h_lagpack[m] = make_float4(lag32, bits_to_float(fi), bits_to_float(ci), 0.f);
    }
    cudaMemcpyToSymbolAsync(g_lagpack, h_lagpack, sizeof(float4) * (size_t)Mc, 0,
                            cudaMemcpyHostToDevice, 0);
    yin_fft_kernel<<<B, 256>>>(x, (float*)d_out, M);
}